// round 15
// baseline (speedup 1.0000x reference)
#include <cuda_runtime.h>
#include <cuda_bf16.h>
#include <cstdint>

// SigmaModel: x(40) -> relu GEMM1(64) -> GEMM2(528 of padded 544) -> symmetric
// 32x32 with exp diag.  B=131072, out fp32 [B,32,32].
// Both GEMMs: mma.sync m16n8k16 bf16, 3-term hi/lo split precision, fp32 acc.
//
// R13: TM=64 / 512-thread structure from R10, with addressing reverted to the
// R8-proven per-kc fully-swizzled offset arrays. (R10/R12 hoisted SW128 out of
// the k-loop; SW128 XOR (bits 4..6 <- bits 7..9) does NOT distribute over
// +kc*32 which occupies bits 5..6 -> wrong fragments -> NaN.)

#define BATCH  131072
#define DIM    32
#define ADIM   8
#define INDIM  40
#define HID    64
#define TRI    528
#define TRIP   544
#define NTHR   512
#define TM     64
#define NTILES (BATCH / TM)
#define SSTR   528

#define OFF_BHI   0          // W2 hi bf16 SW128, 68 atoms (69632 B)
#define OFF_BLO   69632
#define OFF_W1HI  139264     // W1 hi bf16 SW128 [64][64] (8192 B)
#define OFF_W1LO  147456
#define OFF_U     155648     // union: X/A bf16 (32KB) | stage f32 [32][528]
#define OFF_XHI   (OFF_U)
#define OFF_XLO   (OFF_U + 8192)
#define OFF_AHI   (OFF_U + 16384)
#define OFF_ALO   (OFF_U + 24576)
#define OFF_STAGE (OFF_U)
#define OFF_B2    223232     // 544 f32
#define OFF_B1    225408     // 64 f32
#define OFF_LUT   225664     // 1024 u16 (stage byte offsets t*4)
#define SMEM_BYTES 227712

#define SW128(x) ((x) ^ (((x) >> 3) & 0x70))

__device__ __forceinline__ uint32_t smem_u32(const void* p) {
    uint32_t r;
    asm("{ .reg .u64 t; cvta.to.shared.u64 t, %1; cvt.u32.u64 %0, t; }" : "=r"(r) : "l"(p));
    return r;
}
__device__ __forceinline__ void ldsm_x4(uint32_t& r0, uint32_t& r1, uint32_t& r2,
                                        uint32_t& r3, uint32_t addr) {
    asm volatile("ldmatrix.sync.aligned.m8n8.x4.shared.b16 {%0,%1,%2,%3}, [%4];"
                 : "=r"(r0), "=r"(r1), "=r"(r2), "=r"(r3) : "r"(addr));
}
__device__ __forceinline__ void mma_bf16(float* d, const uint32_t* a,
                                         uint32_t b0, uint32_t b1) {
    asm("mma.sync.aligned.m16n8k16.row.col.f32.bf16.bf16.f32 "
        "{%0,%1,%2,%3},{%4,%5,%6,%7},{%8,%9},{%0,%1,%2,%3};"
        : "+f"(d[0]), "+f"(d[1]), "+f"(d[2]), "+f"(d[3])
        : "r"(a[0]), "r"(a[1]), "r"(a[2]), "r"(a[3]), "r"(b0), "r"(b1));
}
// pack (lo_v, hi_v) -> bf16x2 hi; residuals -> bf16x2 lo
__device__ __forceinline__ void split2(float lo_v, float hi_v,
                                       uint32_t& hi, uint32_t& lo) {
    asm("cvt.rn.bf16x2.f32 %0, %1, %2;" : "=r"(hi) : "f"(hi_v), "f"(lo_v));
    float f0 = __uint_as_float(hi << 16);
    float f1 = __uint_as_float(hi & 0xFFFF0000u);
    float r0 = lo_v - f0, r1 = hi_v - f1;
    asm("cvt.rn.bf16x2.f32 %0, %1, %2;" : "=r"(lo) : "f"(r1), "f"(r0));
}

__global__ void __launch_bounds__(NTHR, 1)
sigma_kernel(const float* __restrict__ s,
             const float* __restrict__ a,
             const float* __restrict__ W1,
             const float* __restrict__ b1,
             const float* __restrict__ W2,
             const float* __restrict__ b2,
             float* __restrict__ out)
{
    extern __shared__ char sm[];
    const uint32_t smb = smem_u32(sm);

    const int tid  = threadIdx.x;
    const int wid  = tid >> 5;
    const int lane = tid & 31;

    // ---------------- one-time setup ----------------
    for (int idx = tid; idx < TRIP * HID; idx += NTHR) {           // W2 hi/lo
        int r = idx >> 6, k = idx & 63;
        float w = (r < TRI) ? W2[r * HID + k] : 0.0f;
        uint32_t hi, lo; split2(w, 0.0f, hi, lo);
        uint32_t off = ((r >> 3) << 10) + SW128(((r & 7) << 7) + (k << 1));
        *(uint16_t*)(sm + OFF_BHI + off) = (uint16_t)(hi & 0xFFFF);
        *(uint16_t*)(sm + OFF_BLO + off) = (uint16_t)(lo & 0xFFFF);
    }
    for (int idx = tid; idx < 64 * 64; idx += NTHR) {              // W1 hi/lo (pad k>=40)
        int r = idx >> 6, k = idx & 63;
        float w = (k < INDIM) ? W1[r * INDIM + k] : 0.0f;
        uint32_t hi, lo; split2(w, 0.0f, hi, lo);
        uint32_t off = ((r >> 3) << 10) + SW128(((r & 7) << 7) + (k << 1));
        *(uint16_t*)(sm + OFF_W1HI + off) = (uint16_t)(hi & 0xFFFF);
        *(uint16_t*)(sm + OFF_W1LO + off) = (uint16_t)(lo & 0xFFFF);
    }
    for (int t = tid; t < TRIP; t += NTHR)
        ((float*)(sm + OFF_B2))[t] = (t < TRI) ? b2[t] : 0.0f;
    if (tid < HID) ((float*)(sm + OFF_B1))[tid] = b1[tid];
    for (int idx = tid; idx < DIM * DIM; idx += NTHR) {            // LUT: byte offsets
        int i = idx >> 5, j = idx & 31;
        int ii = min(i, j), jj = max(i, j);
        int t = ii * (2 * DIM + 1 - ii) / 2 + (jj - ii);
        ((uint16_t*)(sm + OFF_LUT))[idx] = (uint16_t)(t * 4);
    }

    // ---------------- per-lane constants (per-kc, fully swizzled) ----------------
    const int mb = wid >> 2, ns = wid & 3;
    uint32_t aoff[4], bsw[4];
    {
        int arow = (mb << 4) + (lane & 15);
        uint32_t a_atom = (uint32_t)(arow >> 3) << 10;
        uint32_t a_row7 = (uint32_t)(arow & 7) << 7;
        uint32_t a_kadd = (uint32_t)(lane >> 4) << 4;
        uint32_t b_row7 = (uint32_t)(lane & 7) << 7;
        uint32_t b_kadd = (uint32_t)((lane >> 3) & 1) << 4;
        #pragma unroll
        for (int kc = 0; kc < 4; ++kc) {
            aoff[kc] = a_atom + SW128(a_row7 + kc * 32 + a_kadd);
            bsw[kc]  = SW128(b_row7 + kc * 32 + b_kadd);
        }
    }
    const uint32_t w1_losel = (lane >= 16) ? 8192u  : 0u;   // W1LO - W1HI
    const uint32_t b_losel  = (lane >= 16) ? 69632u : 0u;   // BLO - BHI

    const int tb = ns * 136 + ((lane & 3) << 1);   // stage col base
    unsigned long long dmask = 0ull;
    #pragma unroll 1
    for (int nt = 0; nt < 17; ++nt) {
        int t0 = tb + (nt << 3);
        for (int i = 0; i < 32; ++i) {
            int di = i * (65 - i) / 2;
            if (di == t0)     dmask |= 1ull << (2 * nt);
            if (di == t0 + 1) dmask |= 1ull << (2 * nt + 1);
        }
    }
    __syncthreads();

    // store-loop invariants
    const int srow = (wid << 1) + (lane >> 4);     // dense row (2 rows/warp)
    const int c0   = (lane & 15) << 1;
    uint32_t toff0, toff1;
    toff0 = ((const uint16_t*)(sm + OFF_LUT))[(srow << 5) + c0];
    toff1 = ((const uint16_t*)(sm + OFF_LUT))[(srow << 5) + c0 + 1];
    const int lane_out = srow * DIM + c0;

    // ---------------- main loop ----------------
    for (int tile = blockIdx.x; tile < NTILES; tile += gridDim.x) {
        const long long ebase = (long long)tile * TM;

        // ---- x-stage: [s|a] -> bf16 hi/lo SW128 (cols 0..39; 40..47 zero) ----
        {
            #pragma unroll
            for (int r = 0; r < 2; ++r) {
                int item = tid + (r << 9);          // 0..1023: s part
                int e = item >> 4, kp = item & 15;
                float2 f = __ldg((const float2*)(s + (ebase + e) * DIM) + kp);
                uint32_t hi, lo; split2(f.x, f.y, hi, lo);
                uint32_t off = ((e >> 3) << 10) + SW128(((e & 7) << 7) + (kp << 2));
                *(uint32_t*)(sm + OFF_XHI + off) = hi;
                *(uint32_t*)(sm + OFF_XLO + off) = lo;
            }
            if (tid < 256) {                        // a part: 64 x 4 float2
                int e = tid >> 2, j = tid & 3, kp = 16 + j;
                float2 f = __ldg((const float2*)(a + (ebase + e) * ADIM) + j);
                uint32_t hi, lo; split2(f.x, f.y, hi, lo);
                uint32_t off = ((e >> 3) << 10) + SW128(((e & 7) << 7) + (kp << 2));
                *(uint32_t*)(sm + OFF_XHI + off) = hi;
                *(uint32_t*)(sm + OFF_XLO + off) = lo;
            }
            {                                       // zero pad cols 40..47
                int e = tid >> 3, w8 = tid & 7, kp = 20 + (w8 & 3);
                uint32_t off = ((e >> 3) << 10) + SW128(((e & 7) << 7) + (kp << 2));
                *(uint32_t*)(sm + ((w8 >> 2) ? OFF_XLO : OFF_XHI) + off) = 0u;
            }
        }
        __syncthreads();

        // ---- GEMM1: h = relu(x @ W1^T + b1) -> A hi/lo ----
        {
            float acc1[2][4];
            #pragma unroll
            for (int n = 0; n < 2; ++n)
                acc1[n][0] = acc1[n][1] = acc1[n][2] = acc1[n][3] = 0.0f;
            #pragma unroll
            for (int kc = 0; kc < 3; ++kc) {
                uint32_t xhi[4], xlo[4];
                ldsm_x4(xhi[0], xhi[1], xhi[2], xhi[3], smb + OFF_XHI + aoff[kc]);
                ldsm_x4(xlo[0], xlo[1], xlo[2], xlo[3], smb + OFF_XLO + aoff[kc]);
                #pragma unroll
                for (int ntl = 0; ntl < 2; ++ntl) {
                    uint32_t ntg = (ns << 1) + ntl;
                    uint32_t wh0, wh1, wl0, wl1;
                    ldsm_x4(wh0, wh1, wl0, wl1,
                            smb + OFF_W1HI + (ntg << 10) + w1_losel + bsw[kc]);
                    mma_bf16(acc1[ntl], xhi, wh0, wh1);
                    mma_bf16(acc1[ntl], xhi, wl0, wl1);
                    mma_bf16(acc1[ntl], xlo, wh0, wh1);
                }
            }
            const float* b1s = (const float*)(sm + OFF_B1);
            int c_lo = (ns << 4) + ((lane & 3) << 1);
            int r0 = (mb << 4) + (lane >> 2);
            int r1 = r0 + 8;
            #pragma unroll
            for (int ntl = 0; ntl < 2; ++ntl) {
                int c = c_lo + (ntl << 3);
                float ba = b1s[c], bbv = b1s[c + 1];
                float v00 = fmaxf(acc1[ntl][0] + ba,  0.0f);
                float v01 = fmaxf(acc1[ntl][1] + bbv, 0.0f);
                float v10 = fmaxf(acc1[ntl][2] + ba,  0.0f);
                float v11 = fmaxf(acc1[ntl][3] + bbv, 0.0f);
                uint32_t hi, lo;
                split2(v00, v01, hi, lo);
                uint32_t off = ((r0 >> 3) << 10) + SW128(((r0 & 7) << 7) + (c << 1));
                *(uint32_t*)(sm + OFF_AHI + off) = hi;
                *(uint32_t*)(sm + OFF_ALO + off) = lo;
                split2(v10, v11, hi, lo);
                off = ((r1 >> 3) << 10) + SW128(((r1 & 7) << 7) + (c << 1));
                *(uint32_t*)(sm + OFF_AHI + off) = hi;
                *(uint32_t*)(sm + OFF_ALO + off) = lo;
            }
        }
        __syncthreads();

        // ---- GEMM2: acc[17][4] = h @ W2^T (3-term split) ----
        float acc[17][4];
        #pragma unroll
        for (int nt = 0; nt < 17; ++nt)
            acc[nt][0] = acc[nt][1] = acc[nt][2] = acc[nt][3] = 0.0f;
        #pragma unroll
        for (int kc = 0; kc < 4; ++kc) {
            uint32_t ahi[4], alo[4];
            ldsm_x4(ahi[0], ahi[1], ahi[2], ahi[3], smb + OFF_AHI + aoff[kc]);
            ldsm_x4(alo[0], alo[1], alo[2], alo[3], smb + OFF_ALO + aoff[kc]);
            uint32_t baddr = smb + OFF_BHI + ((uint32_t)(ns * 17) << 10)
                           + b_losel + bsw[kc];
            #pragma unroll
            for (int nt = 0; nt < 17; ++nt) {
                uint32_t bh0, bh1, bl0, bl1;
                ldsm_x4(bh0, bh1, bl0, bl1, baddr);
                baddr += 1024;
                mma_bf16(acc[nt], ahi, bh0, bh1);
                mma_bf16(acc[nt], ahi, bl0, bl1);
                mma_bf16(acc[nt], alo, bh0, bh1);
            }
        }
        __syncthreads();   // X/A dead; stage may overwrite union

        // ---- epilogue: two rounds of 32 elements ----
        #pragma unroll 1
        for (int r = 0; r < 2; ++r) {
            if ((mb >> 1) == r) {      // stage this half's accumulators
                int er = ((mb & 1) << 4) + (lane >> 2);
                const float* b2s = (const float*)(sm + OFF_B2);
                float* stg = (float*)(sm + OFF_STAGE);
                #pragma unroll
                for (int nt = 0; nt < 17; ++nt) {
                    int t0 = tb + (nt << 3);
                    if (t0 < TRI) {
                        float2 bb = *(const float2*)(b2s + t0);
                        float v0 = acc[nt][0] + bb.x, v1 = acc[nt][1] + bb.y;
                        float v2 = acc[nt][2] + bb.x, v3 = acc[nt][3] + bb.y;
                        if ((dmask >> (2 * nt)) & 1ull) { v0 = __expf(v0); v2 = __expf(v2); }
                        if ((dmask >> (2 * nt + 1)) & 1ull) { v1 = __expf(v1); v3 = __expf(v3); }
                        *(float2*)(stg + er * SSTR + t0)       = make_float2(v0, v1);
                        *(float2*)(stg + (er + 8) * SSTR + t0) = make_float2(v2, v3);
                    }
                }
            }
            __syncthreads();

            {   // store 32 elements, all 16 warps
                const char* sbase = sm + OFF_STAGE;
                float* ob = out + (ebase + (r << 5)) * (DIM * DIM) + lane_out;
                #pragma unroll 4
                for (int e = 0; e < 32; ++e) {
                    const char* srw = sbase + e * (SSTR * 4);
                    float v0 = *(const float*)(srw + toff0);
                    float v1 = *(const float*)(srw + toff1);
                    __stcs((float2*)(ob + e * (DIM * DIM)), make_float2(v0, v1));
                }
            }
            __syncthreads();
        }
    }
}

extern "C" void kernel_launch(void* const* d_in, const int* in_sizes, int n_in,
                              void* d_out, int out_size)
{
    const float* s  = (const float*)d_in[0];
    const float* a  = (const float*)d_in[1];
    const float* W1 = (const float*)d_in[2];
    const float* b1 = (const float*)d_in[3];
    const float* W2 = (const float*)d_in[4];
    const float* b2 = (const float*)d_in[5];
    float* out = (float*)d_out;

    int nsm = 148;
    cudaDeviceGetAttribute(&nsm, cudaDevAttrMultiProcessorCount, 0);

    cudaFuncSetAttribute(sigma_kernel,
                         cudaFuncAttributeMaxDynamicSharedMemorySize, SMEM_BYTES);
    sigma_kernel<<<nsm, NTHR, SMEM_BYTES>>>(s, a, W1, b1, W2, b2, out);
}